// round 10
// baseline (speedup 1.0000x reference)
#include <cuda_runtime.h>
#include <cuda_fp16.h>
#include <cstdint>
#include <cstddef>

#define BTILE    28      // batches per CTA (grid 147 covers 148 SMs in one wave)
#define GPB      4       // batch groups per block
#define BPG      7       // batches per group
#define S_LEN    256
#define F_IN     5
#define HID      64
#define GATES    256
#define NTHREADS 256

typedef unsigned long long ull;

// ---------- packed f32x2 helpers (sm_100a) ----------
__device__ __forceinline__ ull pk2(float a, float b) {
    ull r;
    asm("mov.b64 %0, {%1, %2};" : "=l"(r) : "r"(__float_as_uint(a)), "r"(__float_as_uint(b)));
    return r;
}
__device__ __forceinline__ ull dup2(float a) {
    ull r;
    asm("mov.b64 %0, {%1, %1};" : "=l"(r) : "r"(__float_as_uint(a)));
    return r;
}
__device__ __forceinline__ void unpk(ull v, float& a, float& b) {
    unsigned int lo, hi;
    asm("mov.b64 {%0, %1}, %2;" : "=r"(lo), "=r"(hi) : "l"(v));
    a = __uint_as_float(lo);
    b = __uint_as_float(hi);
}
__device__ __forceinline__ void fma2(ull& d, ull a, ull b) {
    asm("fma.rn.f32x2 %0, %1, %2, %0;" : "+l"(d) : "l"(a), "l"(b));
}

#define BARP(id) asm volatile("bar.sync %0, 64;" :: "r"(id) : "memory")

// ---------- HW tanh activations (MUFU.TANH; validated rel_err ~1.7e-6) ----------
__device__ __forceinline__ float tanhap(float x) {
    float y;
    asm("tanh.approx.f32 %0, %1;" : "=f"(y) : "f"(x));
    return y;
}
__device__ __forceinline__ float sigm(float x) {
    return fmaf(tanhap(0.5f * x), 0.5f, 0.5f);
}

// gate permutation: g = m*64 + cell  ->  p = cell*4 + m
__device__ __forceinline__ int permg(int g) {
    return ((g & 63) << 2) + (g >> 6);
}

__device__ __forceinline__ float cell_update(ull aif, ull ago, float& c) {
    float iv, fv, gv, ov;
    unpk(aif, iv, fv);
    unpk(ago, gv, ov);
    float cn = sigm(fv) * c + sigm(iv) * tanhap(gv);
    c = cn;
    return sigm(ov) * tanhap(cn);
}

// acc[b][0]=(i,f), acc[b][1]=(g,o) for cell C, batches b0..b0+6.
// W stored as fp16 (half crossbar traffic); convert to f32 at use.
__device__ __forceinline__ void gemm7h(const float* __restrict__ hsrc,
                                       const __half* __restrict__ Wsm,
                                       int C, int b0, ull acc[BPG][2]) {
    const __half* wp = Wsm + C * 4;
    #pragma unroll 4
    for (int k4 = 0; k4 < HID; k4 += 4) {
        float4 h4[BPG];
        #pragma unroll
        for (int b = 0; b < BPG; b++)
            h4[b] = *(const float4*)(hsrc + (b0 + b) * HID + k4);
        #pragma unroll
        for (int kk = 0; kk < 4; kk++) {
            uint2 wv = *(const uint2*)(wp + (k4 + kk) * GATES);   // 4 halves: (i,f,g,o)
            float2 fif = __half22float2(*(const __half2*)&wv.x);
            float2 fgo = __half22float2(*(const __half2*)&wv.y);
            ull wif = pk2(fif.x, fif.y);
            ull wgo = pk2(fgo.x, fgo.y);
            #pragma unroll
            for (int b = 0; b < BPG; b++) {
                float hs = (kk == 0) ? h4[b].x : (kk == 1) ? h4[b].y
                         : (kk == 2) ? h4[b].z : h4[b].w;
                ull hv = dup2(hs);
                fma2(acc[b][0], wif, hv);
                fma2(acc[b][1], wgo, hv);
            }
        }
    }
}

__device__ __forceinline__ float mlp_head(const float* __restrict__ hb,
                                          const float* __restrict__ w1,
                                          const float* __restrict__ b1,
                                          const float* __restrict__ w2,
                                          const float* __restrict__ b2) {
    float acc = b2[0];
    #pragma unroll 4
    for (int u = 0; u < 16; u++) {
        float s = b1[u];
        #pragma unroll 8
        for (int k = 0; k < HID; k++) s += hb[k] * w1[u * HID + k];
        acc += fmaxf(s, 0.0f) * w2[u];
    }
    return sigm(acc);
}

__global__ void __launch_bounds__(NTHREADS, 1)
lstm_behavior_kernel(const float* __restrict__ x,
                     const float* __restrict__ w_ih0, const float* __restrict__ w_hh0,
                     const float* __restrict__ b_ih0, const float* __restrict__ b_hh0,
                     const float* __restrict__ w_ih1, const float* __restrict__ w_hh1,
                     const float* __restrict__ b_ih1, const float* __restrict__ b_hh1,
                     const float* __restrict__ eng_w1, const float* __restrict__ eng_b1,
                     const float* __restrict__ eng_w2, const float* __restrict__ eng_b2,
                     const float* __restrict__ prop_w1, const float* __restrict__ prop_b1,
                     const float* __restrict__ prop_w2, const float* __restrict__ prop_b2,
                     const float* __restrict__ seg_w, const float* __restrict__ seg_b,
                     float* __restrict__ out, int Btot) {
    extern __shared__ float smf[];
    // fp16 weight tiles first (each [64][256] halfs = 32KB)
    __half* W0  = (__half*)smf;
    __half* W1i = W0  + HID * GATES;
    __half* W1h = W1i + HID * GATES;
    float*  HA  = (float*)(W1h + HID * GATES);   // [28][64] layer0 h
    float*  HB  = HA + BTILE * HID;              // [28][64] layer1 h
    float*  XS  = HB + BTILE * HID;              // [2][4][35] x staging

    const int tid = threadIdx.x;

    // ---- prologue: load + permute + fp16-quantize recurrent weights ----
    for (int idx = tid; idx < HID * GATES; idx += NTHREADS) {
        int g = idx >> 6, k = idx & 63;
        int p = permg(g);
        W0 [k * GATES + p] = __float2half_rn(w_hh0[idx]);
        W1i[k * GATES + p] = __float2half_rn(w_ih1[idx]);
        W1h[k * GATES + p] = __float2half_rn(w_hh1[idx]);
    }
    for (int idx = tid; idx < BTILE * HID; idx += NTHREADS) {
        HA[idx] = 0.0f;
        HB[idx] = 0.0f;
    }

    const int w    = tid >> 5;
    const int lane = tid & 31;
    const int bg   = w >> 1;          // batch group 0..3 (7 batches each)
    const int ch   = w & 1;           // cell half
    const int C    = ch * 32 + lane;  // my cell 0..63
    const int b0   = bg * BPG;
    const int plid = ch * 32 + lane;  // pair-local tid 0..63
    const int barid = bg + 1;

    // ---- per-thread register-resident weights: WX (w_ih0, fp32) and biases ----
    float4 wxr[F_IN];
    #pragma unroll
    for (int f = 0; f < F_IN; f++) {
        wxr[f].x = w_ih0[(0 * HID + C) * F_IN + f];
        wxr[f].y = w_ih0[(1 * HID + C) * F_IN + f];
        wxr[f].z = w_ih0[(2 * HID + C) * F_IN + f];
        wxr[f].w = w_ih0[(3 * HID + C) * F_IN + f];
    }
    ull b0if = pk2(b_ih0[C] + b_hh0[C],             b_ih0[HID + C] + b_hh0[HID + C]);
    ull b0go = pk2(b_ih0[2 * HID + C] + b_hh0[2 * HID + C],
                   b_ih0[3 * HID + C] + b_hh0[3 * HID + C]);
    ull b1if = pk2(b_ih1[C] + b_hh1[C],             b_ih1[HID + C] + b_hh1[HID + C]);
    ull b1go = pk2(b_ih1[2 * HID + C] + b_hh1[2 * HID + C],
                   b_ih1[3 * HID + C] + b_hh1[3 * HID + C]);

    // ---- x staging setup (clamped for the remainder CTA) ----
    const bool xload = (plid < BPG * F_IN);            // plid < 35
    const int  xb = plid / F_IN, xf = plid - xb * F_IN;
    int gxb = blockIdx.x * BTILE + b0 + xb;
    if (gxb > Btot - 1) gxb = Btot - 1;
    const float* xrow = x + (size_t)gxb * (S_LEN * F_IN) + xf;
    float* xs0 = XS + bg * (BPG * F_IN);               // parity-0 slot
    float* xs1 = XS + (GPB + bg) * (BPG * F_IN);       // parity-1 slot
    const float* xsr0 = xs0;
    const float* xsr1 = xs1;

    float xreg = 0.0f;
    if (xload) {
        xs0[plid] = xrow[0];       // stage t=0
        xreg = xrow[F_IN];         // prefetch t=1
    }

    float cA[BPG], cB[BPG];
    #pragma unroll
    for (int b = 0; b < BPG; b++) { cA[b] = 0.0f; cB[b] = 0.0f; }

    __syncthreads();   // weights + HA/HB zero + XS(0) visible

    for (int t = 0; t < S_LEN; ++t) {
        const float* xcur = (t & 1) ? xsr1 : xsr0;

        // ===== layer 0: gates = B0 + x*W_ih0 + hA(t-1)*W_hh0 =====
        ull acc[BPG][2];
        #pragma unroll
        for (int b = 0; b < BPG; b++) { acc[b][0] = b0if; acc[b][1] = b0go; }
        #pragma unroll
        for (int f = 0; f < F_IN; ++f) {
            ull wif = pk2(wxr[f].x, wxr[f].y);
            ull wgo = pk2(wxr[f].z, wxr[f].w);
            #pragma unroll
            for (int b = 0; b < BPG; b++) {
                ull xv = dup2(xcur[b * F_IN + f]);
                fma2(acc[b][0], wif, xv);
                fma2(acc[b][1], wgo, xv);
            }
        }
        gemm7h(HA, W0, C, b0, acc);

        float hn[BPG];
        #pragma unroll
        for (int b = 0; b < BPG; b++)
            hn[b] = cell_update(acc[b][0], acc[b][1], cA[b]);

        BARP(barid);                         // pair done reading HA(t-1)
        #pragma unroll
        for (int b = 0; b < BPG; b++)
            HA[(b0 + b) * HID + C] = hn[b];
        BARP(barid);                         // HA(t) visible

        // ===== layer 1: gates = B1 + hA(t)*W_ih1 + hB(t-1)*W_hh1 =====
        #pragma unroll
        for (int b = 0; b < BPG; b++) { acc[b][0] = b1if; acc[b][1] = b1go; }
        gemm7h(HA, W1i, C, b0, acc);
        gemm7h(HB, W1h, C, b0, acc);

        // stage x(t+1) into the other parity buffer; prefetch x(t+2)
        if (xload) {
            float* xnxt = (t & 1) ? xs0 : xs1;
            xnxt[plid] = xreg;
            int tn = (t + 2 < S_LEN) ? (t + 2) : (S_LEN - 1);
            xreg = xrow[tn * F_IN];
        }

        #pragma unroll
        for (int b = 0; b < BPG; b++)
            hn[b] = cell_update(acc[b][0], acc[b][1], cB[b]);

        BARP(barid);                         // HB(t-1) reads done; XS(t+1) visible
        #pragma unroll
        for (int b = 0; b < BPG; b++)
            HB[(b0 + b) * HID + C] = hn[b];
        // HB(t) visibility: next iteration's first BARP
    }
    __syncthreads();   // final HB visible block-wide

    // ---- heads: one thread per batch element of this tile (fp32 weights) ----
    if (tid < BTILE) {
        int b = blockIdx.x * BTILE + tid;
        if (b < Btot) {
            const float* hb = HB + tid * HID;
            out[b]        = mlp_head(hb, eng_w1, eng_b1, eng_w2, eng_b2);
            out[Btot + b] = mlp_head(hb, prop_w1, prop_b1, prop_w2, prop_b2);
            #pragma unroll
            for (int j = 0; j < 5; j++) {
                float s = seg_b[j];
                #pragma unroll 8
                for (int k = 0; k < HID; k++) s += hb[k] * seg_w[j * HID + k];
                out[2 * Btot + b * 5 + j] = s;
            }
        }
    }
}

extern "C" void kernel_launch(void* const* d_in, const int* in_sizes, int n_in,
                              void* d_out, int out_size) {
    const float* x       = (const float*)d_in[0];
    const float* w_ih0   = (const float*)d_in[1];
    const float* w_hh0   = (const float*)d_in[2];
    const float* b_ih0   = (const float*)d_in[3];
    const float* b_hh0   = (const float*)d_in[4];
    const float* w_ih1   = (const float*)d_in[5];
    const float* w_hh1   = (const float*)d_in[6];
    const float* b_ih1   = (const float*)d_in[7];
    const float* b_hh1   = (const float*)d_in[8];
    const float* eng_w1  = (const float*)d_in[9];
    const float* eng_b1  = (const float*)d_in[10];
    const float* eng_w2  = (const float*)d_in[11];
    const float* eng_b2  = (const float*)d_in[12];
    const float* prop_w1 = (const float*)d_in[13];
    const float* prop_b1 = (const float*)d_in[14];
    const float* prop_w2 = (const float*)d_in[15];
    const float* prop_b2 = (const float*)d_in[16];
    const float* seg_w   = (const float*)d_in[17];
    const float* seg_b   = (const float*)d_in[18];
    float* out = (float*)d_out;

    int Btot = in_sizes[0] / (S_LEN * F_IN);        // 4096
    int grid = (Btot + BTILE - 1) / BTILE;          // 147

    // 3 fp16 W tiles (96KB) + fp32 state/staging
    size_t smem = (size_t)(3 * HID * GATES) * sizeof(__half) +
                  (size_t)(2 * BTILE * HID + 2 * GPB * BPG * F_IN) * sizeof(float);
    cudaFuncSetAttribute(lstm_behavior_kernel,
                         cudaFuncAttributeMaxDynamicSharedMemorySize, (int)smem);

    lstm_behavior_kernel<<<grid, NTHREADS, smem>>>(
        x, w_ih0, w_hh0, b_ih0, b_hh0, w_ih1, w_hh1, b_ih1, b_hh1,
        eng_w1, eng_b1, eng_w2, eng_b2, prop_w1, prop_b1, prop_w2, prop_b2,
        seg_w, seg_b, out, Btot);
}

// round 12
// speedup vs baseline: 2.8684x; 2.8684x over previous
#include <cuda_runtime.h>
#include <cuda_fp16.h>
#include <cstdint>
#include <cstddef>

#define BTILE  28
#define S_LEN  256
#define F_IN   5
#define HID    64
#define NTH    256

#define KP0    88          // padded k (fp16 elems) layer0 rows (80 used)
#define KP1    136         // padded k layer1 rows (128 used)
#define SGP    36          // gate-bounce pad (f32 per gate row)
#define KT0    5           // k16 tiles layer0
#define KT1    8           // k16 tiles layer1

// SMEM byte offsets
#define SM_WA0 0
#define SM_WA1 (SM_WA0 + 256 * KP0 * 2)        // 45056
#define SM_B0  (SM_WA1 + 256 * KP1 * 2)        // 114688
#define SM_B1  (SM_B0 + 32 * KP0 * 2)          // 120320
#define SM_SG  (SM_B1 + 32 * KP1 * 2)          // 129024
#define SM_HBF (SM_SG + 256 * SGP * 4)         // 165888
#define SM_TOT (SM_HBF + BTILE * HID * 4)      // 173056

__device__ __forceinline__ uint32_t smem_u32(const void* p) {
    uint32_t a;
    asm("{ .reg .u64 t; cvta.to.shared.u64 t, %1; cvt.u32.u64 %0, t; }" : "=r"(a) : "l"(p));
    return a;
}
__device__ __forceinline__ uint32_t lds32(uint32_t a) {
    uint32_t v;
    asm volatile("ld.shared.b32 %0, [%1];" : "=r"(v) : "r"(a));
    return v;
}
__device__ __forceinline__ void sts64f(uint32_t a, float x, float y) {
    asm volatile("st.shared.v2.f32 [%0], {%1, %2};" :: "r"(a), "f"(x), "f"(y) : "memory");
}

// m16n8k16 row.col f32 += f16*f16 (classic HMMA — plain sm_80+ PTX)
__device__ __forceinline__ void mma16816(float* c, const uint32_t* a, const uint32_t* b) {
    asm volatile(
        "mma.sync.aligned.m16n8k16.row.col.f32.f16.f16.f32 "
        "{%0,%1,%2,%3}, {%4,%5,%6,%7}, {%8,%9}, {%0,%1,%2,%3};"
        : "+f"(c[0]), "+f"(c[1]), "+f"(c[2]), "+f"(c[3])
        : "r"(a[0]), "r"(a[1]), "r"(a[2]), "r"(a[3]), "r"(b[0]), "r"(b[1]));
}

// ---------- activations (MUFU.TANH; validated) ----------
__device__ __forceinline__ float tanhap(float x) {
    float y;
    asm("tanh.approx.f32 %0, %1;" : "=f"(y) : "f"(x));
    return y;
}
__device__ __forceinline__ float sigm(float x) {
    return fmaf(tanhap(0.5f * x), 0.5f, 0.5f);
}

__device__ __forceinline__ float mlp_head(const float* __restrict__ hb,
                                          const float* __restrict__ w1,
                                          const float* __restrict__ b1,
                                          const float* __restrict__ w2,
                                          const float* __restrict__ b2) {
    float acc = b2[0];
    #pragma unroll 4
    for (int u = 0; u < 16; u++) {
        float s = b1[u];
        #pragma unroll 8
        for (int k = 0; k < HID; k++) s += hb[k] * w1[u * HID + k];
        acc += fmaxf(s, 0.0f) * w2[u];
    }
    return sigm(acc);
}

// per-warp gemm: gates[w*32 .. w*32+31][0..31] += A(rows)·B  (fp16 in, fp32 acc)
__device__ __forceinline__ void gemm_layer(uint32_t waBase, uint32_t bBase,
                                           int rowB, int ktc,
                                           int w, int gid, int tg,
                                           float C[2][4][4]) {
    #pragma unroll
    for (int kt = 0; kt < 8; kt++) {
        if (kt >= ktc) break;
        uint32_t B[4][2];
        #pragma unroll
        for (int nt = 0; nt < 4; nt++) {
            uint32_t ba = bBase + (nt * 8 + gid) * rowB + (kt * 16 + 2 * tg) * 2;
            B[nt][0] = lds32(ba);        // k = 2tg, 2tg+1   @ n = gid
            B[nt][1] = lds32(ba + 16);   // k = 2tg+8, 2tg+9
        }
        #pragma unroll
        for (int mt = 0; mt < 2; mt++) {
            uint32_t ra = waBase + (w * 32 + mt * 16 + gid) * rowB + (kt * 16 + 2 * tg) * 2;
            uint32_t A[4];
            A[0] = lds32(ra);                 // (gid,   2tg..)
            A[1] = lds32(ra + 8 * rowB);      // (gid+8, 2tg..)
            A[2] = lds32(ra + 16);            // (gid,   2tg+8..)
            A[3] = lds32(ra + 8 * rowB + 16); // (gid+8, 2tg+8..)
            #pragma unroll
            for (int nt = 0; nt < 4; nt++)
                mma16816(C[mt][nt], A, B[nt]);
        }
    }
}

__device__ __forceinline__ void store_gates(uint32_t sgBase, int w, int gid, int tg,
                                            float C[2][4][4]) {
    #pragma unroll
    for (int mt = 0; mt < 2; mt++) {
        #pragma unroll
        for (int nt = 0; nt < 4; nt++) {
            uint32_t sa = sgBase +
                (uint32_t)((w * 32 + mt * 16 + gid) * SGP + nt * 8 + 2 * tg) * 4;
            sts64f(sa,                C[mt][nt][0], C[mt][nt][1]);   // row gid
            sts64f(sa + 8 * SGP * 4,  C[mt][nt][2], C[mt][nt][3]);   // row gid+8
        }
    }
}

__global__ void __launch_bounds__(NTH, 1)
lstm_behavior_kernel(const float* __restrict__ x,
                     const float* __restrict__ w_ih0, const float* __restrict__ w_hh0,
                     const float* __restrict__ b_ih0, const float* __restrict__ b_hh0,
                     const float* __restrict__ w_ih1, const float* __restrict__ w_hh1,
                     const float* __restrict__ b_ih1, const float* __restrict__ b_hh1,
                     const float* __restrict__ eng_w1, const float* __restrict__ eng_b1,
                     const float* __restrict__ eng_w2, const float* __restrict__ eng_b2,
                     const float* __restrict__ prop_w1, const float* __restrict__ prop_b1,
                     const float* __restrict__ prop_w2, const float* __restrict__ prop_b2,
                     const float* __restrict__ seg_w, const float* __restrict__ seg_b,
                     float* __restrict__ out, int Btot) {
    extern __shared__ char smem[];
    const uint32_t sb = smem_u32(smem);
    const int tid  = threadIdx.x;
    const int w    = tid >> 5, lane = tid & 31;
    const int gid  = lane >> 2, tg = lane & 3;

    // ---- prologue: zero WA/B regions, fill fp16 weight tiles ----
    for (int i = tid; i < SM_SG / 4; i += NTH)
        ((uint32_t*)smem)[i] = 0;
    __syncthreads();

    for (int idx = tid; idx < 256 * HID; idx += NTH) {
        int g = idx >> 6, k = idx & 63;
        *(__half*)(smem + SM_WA0 + (g * KP0 + k) * 2)        = __float2half_rn(w_hh0[idx]);
        *(__half*)(smem + SM_WA1 + (g * KP1 + k) * 2)        = __float2half_rn(w_ih1[idx]);
        *(__half*)(smem + SM_WA1 + (g * KP1 + 64 + k) * 2)   = __float2half_rn(w_hh1[idx]);
    }
    for (int idx = tid; idx < 256 * F_IN; idx += NTH) {
        int g = idx / F_IN, f = idx - g * F_IN;
        *(__half*)(smem + SM_WA0 + (g * KP0 + 64 + f) * 2)   = __float2half_rn(w_ih0[idx]);
    }

    // ---- update-role constants ----
    const int c  = tid & 63;          // my cell
    const int bq = tid >> 6;          // my 7-batch quarter
    float bz0[4], bz1[4];
    #pragma unroll
    for (int m = 0; m < 4; m++) {
        bz0[m] = b_ih0[m * HID + c] + b_hh0[m * HID + c];
        bz1[m] = b_ih1[m * HID + c] + b_hh1[m * HID + c];
    }
    float cA[7], cB[7];
    #pragma unroll
    for (int j = 0; j < 7; j++) { cA[j] = 0.0f; cB[j] = 0.0f; }

    // ---- x staging ----
    const float* xptr = nullptr;
    float xreg = 0.0f;
    int xoff = 0;
    if (tid < BTILE * F_IN) {
        int xb = tid / F_IN, xf = tid - xb * F_IN;
        int gxb = blockIdx.x * BTILE + xb;
        if (gxb > Btot - 1) gxb = Btot - 1;
        xptr = x + (size_t)gxb * (S_LEN * F_IN) + xf;
        xoff = SM_B0 + (xb * KP0 + 64 + xf) * 2;
        *(__half*)(smem + xoff) = __float2half_rn(xptr[0]);   // x(0)
        xreg = xptr[F_IN];                                    // prefetch x(1)
    }
    float* SGf  = (float*)(smem + SM_SG);
    float* HBF  = (float*)(smem + SM_HBF);
    __syncthreads();

    float C[2][4][4];

    for (int t = 0; t < S_LEN; ++t) {
        // ===== phase 1: L0 gemm  gates0 = W0h·hA(t-1) + W0x·x(t) =====
        #pragma unroll
        for (int a = 0; a < 2; a++)
            #pragma unroll
            for (int b = 0; b < 4; b++)
                #pragma unroll
                for (int e = 0; e < 4; e++) C[a][b][e] = 0.0f;
        gemm_layer(sb + SM_WA0, sb + SM_B0, KP0 * 2, KT0, w, gid, tg, C);
        store_gates(sb + SM_SG, w, gid, tg, C);
        __syncthreads();

        // ===== phase 2: L0 cell update; write hA(t) -> B0(k<64), B1(k<64); stage x(t+1) =====
        #pragma unroll
        for (int j = 0; j < 7; j++) {
            int b = bq * 7 + j;
            float gi = SGf[(0 * HID + c) * SGP + b] + bz0[0];
            float gf = SGf[(1 * HID + c) * SGP + b] + bz0[1];
            float gg = SGf[(2 * HID + c) * SGP + b] + bz0[2];
            float go = SGf[(3 * HID + c) * SGP + b] + bz0[3];
            float cn = sigm(gf) * cA[j] + sigm(gi) * tanhap(gg);
            cA[j] = cn;
            __half hh = __float2half_rn(sigm(go) * tanhap(cn));
            *(__half*)(smem + SM_B0 + (b * KP0 + c) * 2) = hh;
            *(__half*)(smem + SM_B1 + (b * KP1 + c) * 2) = hh;
        }
        if (tid < BTILE * F_IN) {
            *(__half*)(smem + xoff) = __float2half_rn(xreg);
            int tn = (t + 2 < S_LEN) ? (t + 2) : (S_LEN - 1);
            xreg = xptr[tn * F_IN];
        }
        __syncthreads();

        // ===== phase 3: L1 gemm  gates1 = W1i·hA(t) + W1h·hB(t-1) =====
        #pragma unroll
        for (int a = 0; a < 2; a++)
            #pragma unroll
            for (int b = 0; b < 4; b++)
                #pragma unroll
                for (int e = 0; e < 4; e++) C[a][b][e] = 0.0f;
        gemm_layer(sb + SM_WA1, sb + SM_B1, KP1 * 2, KT1, w, gid, tg, C);
        store_gates(sb + SM_SG, w, gid, tg, C);
        __syncthreads();

        // ===== phase 4: L1 cell update; write hB(t) -> B1(k 64..127) =====
        #pragma unroll
        for (int j = 0; j < 7; j++) {
            int b = bq * 7 + j;
            float gi = SGf[(0 * HID + c) * SGP + b] + bz1[0];
            float gf = SGf[(1 * HID + c) * SGP + b] + bz1[1];
            float gg = SGf[(2 * HID + c) * SGP + b] + bz1[2];
            float go = SGf[(3 * HID + c) * SGP + b] + bz1[3];
            float cn = sigm(gf) * cB[j] + sigm(gi) * tanhap(gg);
            cB[j] = cn;
            float h = sigm(go) * tanhap(cn);
            *(__half*)(smem + SM_B1 + (b * KP1 + 64 + c) * 2) = __float2half_rn(h);
            if (t == S_LEN - 1) HBF[b * HID + c] = h;
        }
        __syncthreads();
    }

    // ---- heads ----
    if (tid < BTILE) {
        int b = blockIdx.x * BTILE + tid;
        if (b < Btot) {
            const float* hb = HBF + tid * HID;
            out[b]        = mlp_head(hb, eng_w1, eng_b1, eng_w2, eng_b2);
            out[Btot + b] = mlp_head(hb, prop_w1, prop_b1, prop_w2, prop_b2);
            #pragma unroll
            for (int j = 0; j < 5; j++) {
                float s = seg_b[j];
                #pragma unroll 8
                for (int k = 0; k < HID; k++) s += hb[k] * seg_w[j * HID + k];
                out[2 * Btot + b * 5 + j] = s;
            }
        }
    }
}

extern "C" void kernel_launch(void* const* d_in, const int* in_sizes, int n_in,
                              void* d_out, int out_size) {
    const float* x       = (const float*)d_in[0];
    const float* w_ih0   = (const float*)d_in[1];
    const float* w_hh0   = (const float*)d_in[2];
    const float* b_ih0   = (const float*)d_in[3];
    const float* b_hh0   = (const float*)d_in[4];
    const float* w_ih1   = (const float*)d_in[5];
    const float* w_hh1   = (const float*)d_in[6];
    const float* b_ih1   = (const float*)d_in[7];
    const float* b_hh1   = (const float*)d_in[8];
    const float* eng_w1  = (const float*)d_in[9];
    const float* eng_b1  = (const float*)d_in[10];
    const float* eng_w2  = (const float*)d_in[11];
    const float* eng_b2  = (const float*)d_in[12];
    const float* prop_w1 = (const float*)d_in[13];
    const float* prop_b1 = (const float*)d_in[14];
    const float* prop_w2 = (const float*)d_in[15];
    const float* prop_b2 = (const float*)d_in[16];
    const float* seg_w   = (const float*)d_in[17];
    const float* seg_b   = (const float*)d_in[18];
    float* out = (float*)d_out;

    int Btot = in_sizes[0] / (S_LEN * F_IN);        // 4096
    int grid = (Btot + BTILE - 1) / BTILE;          // 147

    cudaFuncSetAttribute(lstm_behavior_kernel,
                         cudaFuncAttributeMaxDynamicSharedMemorySize, SM_TOT);

    lstm_behavior_kernel<<<grid, NTH, SM_TOT>>>(
        x, w_ih0, w_hh0, b_ih0, b_hh0, w_ih1, w_hh1, b_ih1, b_hh1,
        eng_w1, eng_b1, eng_w2, eng_b2, prop_w1, prop_b1, prop_w2, prop_b2,
        seg_w, seg_b, out, Btot);
}

// round 13
// speedup vs baseline: 3.4449x; 1.2010x over previous
#include <cuda_runtime.h>
#include <cuda_fp16.h>
#include <cstdint>
#include <cstddef>

#define BTILE  28
#define S_LEN  256
#define F_IN   5
#define HID    64
#define NTH    256

#define KP0    88          // B0/WA0 row length (fp16): 80 used, stride 44 words (≡12 mod 32)
#define KP1    152         // B1/WA1 row length (fp16): 128 used, stride 76 words (≡12 mod 32)
#define GP     260         // gate-bounce row stride in f32 words (≡4 mod 32)
#define KT0    5           // k16 tiles layer0
#define KT1    8           // k16 tiles layer1

// SMEM byte offsets
#define SM_WA0 0
#define SM_WA1 (SM_WA0 + 256 * KP0 * 2)        // 45056
#define SM_B0  (SM_WA1 + 256 * KP1 * 2)        // 122880
#define SM_B1  (SM_B0 + 32 * KP0 * 2)          // 128512
#define SM_SG  (SM_B1 + 32 * KP1 * 2)          // 138240
#define SM_HBF (SM_SG + 32 * GP * 4)           // 171520
#define SM_TOT (SM_HBF + BTILE * HID * 4)      // 178688

__device__ __forceinline__ uint32_t smem_u32(const void* p) {
    uint32_t a;
    asm("{ .reg .u64 t; cvta.to.shared.u64 t, %1; cvt.u32.u64 %0, t; }" : "=r"(a) : "l"(p));
    return a;
}
__device__ __forceinline__ uint32_t lds32(uint32_t a) {
    uint32_t v;
    asm volatile("ld.shared.b32 %0, [%1];" : "=r"(v) : "r"(a));
    return v;
}

// m16n8k16 row.col f32 += f16*f16 (plain sm_80+ PTX — compiles at compute_100)
__device__ __forceinline__ void mma16816(float* c, const uint32_t* a, const uint32_t* b) {
    asm volatile(
        "mma.sync.aligned.m16n8k16.row.col.f32.f16.f16.f32 "
        "{%0,%1,%2,%3}, {%4,%5,%6,%7}, {%8,%9}, {%0,%1,%2,%3};"
        : "+f"(c[0]), "+f"(c[1]), "+f"(c[2]), "+f"(c[3])
        : "r"(a[0]), "r"(a[1]), "r"(a[2]), "r"(a[3]), "r"(b[0]), "r"(b[1]));
}

// ---------- activations ----------
__device__ __forceinline__ float tanhap(float x) {
    float y;
    asm("tanh.approx.f32 %0, %1;" : "=f"(y) : "f"(x));
    return y;
}
__device__ __forceinline__ float sigm(float x) {
    return fmaf(tanhap(0.5f * x), 0.5f, 0.5f);
}

__device__ __forceinline__ float mlp_head(const float* __restrict__ hb,
                                          const float* __restrict__ w1,
                                          const float* __restrict__ b1,
                                          const float* __restrict__ w2,
                                          const float* __restrict__ b2) {
    float acc = b2[0];
    #pragma unroll 4
    for (int u = 0; u < 16; u++) {
        float s = b1[u];
        #pragma unroll 8
        for (int k = 0; k < HID; k++) s += hb[k] * w1[u * HID + k];
        acc += fmaxf(s, 0.0f) * w2[u];
    }
    return sigm(acc);
}

__global__ void __launch_bounds__(NTH, 1)
lstm_behavior_kernel(const float* __restrict__ x,
                     const float* __restrict__ w_ih0, const float* __restrict__ w_hh0,
                     const float* __restrict__ b_ih0, const float* __restrict__ b_hh0,
                     const float* __restrict__ w_ih1, const float* __restrict__ w_hh1,
                     const float* __restrict__ b_ih1, const float* __restrict__ b_hh1,
                     const float* __restrict__ eng_w1, const float* __restrict__ eng_b1,
                     const float* __restrict__ eng_w2, const float* __restrict__ eng_b2,
                     const float* __restrict__ prop_w1, const float* __restrict__ prop_b1,
                     const float* __restrict__ prop_w2, const float* __restrict__ prop_b2,
                     const float* __restrict__ seg_w, const float* __restrict__ seg_b,
                     float* __restrict__ out, int Btot) {
    extern __shared__ char smem[];
    const uint32_t sb = smem_u32(smem);
    const int tid  = threadIdx.x;
    const int w    = tid >> 5, lane = tid & 31;
    const int gid  = lane >> 2, tg = lane & 3;

    // ---- prologue: zero weight/B regions, fill fp16 weight tiles ----
    for (int i = tid; i < SM_SG / 4; i += NTH)
        ((uint32_t*)smem)[i] = 0;
    __syncthreads();

    for (int idx = tid; idx < 256 * HID; idx += NTH) {
        int g = idx >> 6, k = idx & 63;
        *(__half*)(smem + SM_WA0 + (g * KP0 + k) * 2)        = __float2half_rn(w_hh0[idx]);
        *(__half*)(smem + SM_WA1 + (g * KP1 + k) * 2)        = __float2half_rn(w_ih1[idx]);
        *(__half*)(smem + SM_WA1 + (g * KP1 + 64 + k) * 2)   = __float2half_rn(w_hh1[idx]);
    }
    for (int idx = tid; idx < 256 * F_IN; idx += NTH) {
        int g = idx / F_IN, f = idx - g * F_IN;
        *(__half*)(smem + SM_WA0 + (g * KP0 + 64 + f) * 2)   = __float2half_rn(w_ih0[idx]);
    }
    __syncthreads();

    // ---- hoist A fragments (constant all 256 steps) into registers ----
    uint32_t aL0[KT0][2][4], aL1[KT1][2][4];
    #pragma unroll
    for (int kt = 0; kt < KT0; kt++)
        #pragma unroll
        for (int mt = 0; mt < 2; mt++) {
            uint32_t ra = sb + SM_WA0 + (uint32_t)((w * 32 + mt * 16 + gid) * KP0 + kt * 16 + 2 * tg) * 2;
            aL0[kt][mt][0] = lds32(ra);
            aL0[kt][mt][1] = lds32(ra + 8 * KP0 * 2);
            aL0[kt][mt][2] = lds32(ra + 16);
            aL0[kt][mt][3] = lds32(ra + 8 * KP0 * 2 + 16);
        }
    #pragma unroll
    for (int kt = 0; kt < KT1; kt++)
        #pragma unroll
        for (int mt = 0; mt < 2; mt++) {
            uint32_t ra = sb + SM_WA1 + (uint32_t)((w * 32 + mt * 16 + gid) * KP1 + kt * 16 + 2 * tg) * 2;
            aL1[kt][mt][0] = lds32(ra);
            aL1[kt][mt][1] = lds32(ra + 8 * KP1 * 2);
            aL1[kt][mt][2] = lds32(ra + 16);
            aL1[kt][mt][3] = lds32(ra + 8 * KP1 * 2 + 16);
        }

    // ---- update-role constants ----
    const int c  = tid & 63;          // my cell
    const int bq = tid >> 6;          // my 7-batch quarter
    float bz0[4], bz1[4];
    #pragma unroll
    for (int m = 0; m < 4; m++) {
        bz0[m] = b_ih0[m * HID + c] + b_hh0[m * HID + c];
        bz1[m] = b_ih1[m * HID + c] + b_hh1[m * HID + c];
    }
    float cA[7], cB[7];
    #pragma unroll
    for (int j = 0; j < 7; j++) { cA[j] = 0.0f; cB[j] = 0.0f; }

    // ---- x staging ----
    const float* xptr = nullptr;
    float xreg = 0.0f;
    int xoff = 0;
    if (tid < BTILE * F_IN) {
        int xb = tid / F_IN, xf = tid - xb * F_IN;
        int gxb = blockIdx.x * BTILE + xb;
        if (gxb > Btot - 1) gxb = Btot - 1;
        xptr = x + (size_t)gxb * (S_LEN * F_IN) + xf;
        xoff = SM_B0 + (xb * KP0 + 64 + xf) * 2;
        *(__half*)(smem + xoff) = __float2half_rn(xptr[0]);
        xreg = xptr[F_IN];
    }
    float* SGf = (float*)(smem + SM_SG);
    float* HBF = (float*)(smem + SM_HBF);
    __syncthreads();

    float C[2][4][4];
    const int grow = w * 32 + gid;    // my base gate row

    for (int t = 0; t < S_LEN; ++t) {
        // ===== phase 1: L0 gemm  gates0 = W0h·hA(t-1) + W0x·x(t) =====
        #pragma unroll
        for (int a = 0; a < 2; a++)
            #pragma unroll
            for (int b = 0; b < 4; b++)
                #pragma unroll
                for (int e = 0; e < 4; e++) C[a][b][e] = 0.0f;
        #pragma unroll
        for (int kt = 0; kt < KT0; kt++) {
            uint32_t B[4][2];
            #pragma unroll
            for (int nt = 0; nt < 4; nt++) {
                uint32_t ba = sb + SM_B0 + (uint32_t)((nt * 8 + gid) * KP0 + kt * 16 + 2 * tg) * 2;
                B[nt][0] = lds32(ba);
                B[nt][1] = lds32(ba + 16);
            }
            #pragma unroll
            for (int mt = 0; mt < 2; mt++)
                #pragma unroll
                for (int nt = 0; nt < 4; nt++)
                    mma16816(C[mt][nt], aL0[kt][mt], B[nt]);
        }
        // store gates: [batch][gate] layout, GP=260 (conflict-free both sides)
        #pragma unroll
        for (int mt = 0; mt < 2; mt++) {
            int g = grow + mt * 16;
            #pragma unroll
            for (int nt = 0; nt < 4; nt++) {
                int b = nt * 8 + 2 * tg;
                SGf[b * GP + g]           = C[mt][nt][0];
                SGf[(b + 1) * GP + g]     = C[mt][nt][1];
                SGf[b * GP + g + 8]       = C[mt][nt][2];
                SGf[(b + 1) * GP + g + 8] = C[mt][nt][3];
            }
        }
        __syncthreads();

        // ===== phase 2: L0 cell update; hA(t) -> B0, B1; stage x(t+1) =====
        #pragma unroll
        for (int j = 0; j < 7; j++) {
            int b = bq * 7 + j;
            const float* gr = SGf + b * GP;
            float gi = gr[c]           + bz0[0];
            float gf = gr[HID + c]     + bz0[1];
            float gg = gr[2 * HID + c] + bz0[2];
            float go = gr[3 * HID + c] + bz0[3];
            float cn = sigm(gf) * cA[j] + sigm(gi) * tanhap(gg);
            cA[j] = cn;
            __half hh = __float2half_rn(sigm(go) * tanhap(cn));
            *(__half*)(smem + SM_B0 + (b * KP0 + c) * 2) = hh;
            *(__half*)(smem + SM_B1 + (b * KP1 + c) * 2) = hh;
        }
        if (tid < BTILE * F_IN) {
            *(__half*)(smem + xoff) = __float2half_rn(xreg);
            int tn = (t + 2 < S_LEN) ? (t + 2) : (S_LEN - 1);
            xreg = xptr[tn * F_IN];
        }
        __syncthreads();

        // ===== phase 3: L1 gemm  gates1 = W1i·hA(t) + W1h·hB(t-1) =====
        #pragma unroll
        for (int a = 0; a < 2; a++)
            #pragma unroll
            for (int b = 0; b < 4; b++)
                #pragma unroll
                for (int e = 0; e < 4; e++) C[a][b][e] = 0.0f;
        #pragma unroll
        for (int kt = 0; kt < KT1; kt++) {
            uint32_t B[4][2];
            #pragma unroll
            for (int nt = 0; nt < 4; nt++) {
                uint32_t ba = sb + SM_B1 + (uint32_t)((nt * 8 + gid) * KP1 + kt * 16 + 2 * tg) * 2;
                B[nt][0] = lds32(ba);
                B[nt][1] = lds32(ba + 16);
            }
            #pragma unroll
            for (int mt = 0; mt < 2; mt++)
                #pragma unroll
                for (int nt = 0; nt < 4; nt++)
                    mma16816(C[mt][nt], aL1[kt][mt], B[nt]);
        }
        #pragma unroll
        for (int mt = 0; mt < 2; mt++) {
            int g = grow + mt * 16;
            #pragma unroll
            for (int nt = 0; nt < 4; nt++) {
                int b = nt * 8 + 2 * tg;
                SGf[b * GP + g]           = C[mt][nt][0];
                SGf[(b + 1) * GP + g]     = C[mt][nt][1];
                SGf[b * GP + g + 8]       = C[mt][nt][2];
                SGf[(b + 1) * GP + g + 8] = C[mt][nt][3];
            }
        }
        __syncthreads();

        // ===== phase 4: L1 cell update; hB(t) -> B1 (cols 64..127) =====
        #pragma unroll
        for (int j = 0; j < 7; j++) {
            int b = bq * 7 + j;
            const float* gr = SGf + b * GP;
            float gi = gr[c]           + bz1[0];
            float gf = gr[HID + c]     + bz1[1];
            float gg = gr[2 * HID + c] + bz1[2];
            float go = gr[3 * HID + c] + bz1[3];
            float cn = sigm(gf) * cB[j] + sigm(gi) * tanhap(gg);
            cB[j] = cn;
            float h = sigm(go) * tanhap(cn);
            *(__half*)(smem + SM_B1 + (b * KP1 + 64 + c) * 2) = __float2half_rn(h);
            if (t == S_LEN - 1) HBF[b * HID + c] = h;
        }
        __syncthreads();
    }

    // ---- heads ----
    if (tid < BTILE) {
        int b = blockIdx.x * BTILE + tid;
        if (b < Btot) {
            const float* hb = HBF + tid * HID;
            out[b]        = mlp_head(hb, eng_w1, eng_b1, eng_w2, eng_b2);
            out[Btot + b] = mlp_head(hb, prop_w1, prop_b1, prop_w2, prop_b2);
            #pragma unroll
            for (int j = 0; j < 5; j++) {
                float s = seg_b[j];
                #pragma unroll 8
                for (int k = 0; k < HID; k++) s += hb[k] * seg_w[j * HID + k];
                out[2 * Btot + b * 5 + j] = s;
            }
        }
    }
}

extern "C" void kernel_launch(void* const* d_in, const int* in_sizes, int n_in,
                              void* d_out, int out_size) {
    const float* x       = (const float*)d_in[0];
    const float* w_ih0   = (const float*)d_in[1];
    const float* w_hh0   = (const float*)d_in[2];
    const float* b_ih0   = (const float*)d_in[3];
    const float* b_hh0   = (const float*)d_in[4];
    const float* w_ih1   = (const float*)d_in[5];
    const float* w_hh1   = (const float*)d_in[6];
    const float* b_ih1   = (const float*)d_in[7];
    const float* b_hh1   = (const float*)d_in[8];
    const float* eng_w1  = (const float*)d_in[9];
    const float* eng_b1  = (const float*)d_in[10];
    const float* eng_w2  = (const float*)d_in[11];
    const float* eng_b2  = (const float*)d_in[12];
    const float* prop_w1 = (const float*)d_in[13];
    const float* prop_b1 = (const float*)d_in[14];
    const float* prop_w2 = (const float*)d_in[15];
    const float* prop_b2 = (const float*)d_in[16];
    const float* seg_w   = (const float*)d_in[17];
    const float* seg_b   = (const float*)d_in[18];
    float* out = (float*)d_out;

    int Btot = in_sizes[0] / (S_LEN * F_IN);        // 4096
    int grid = (Btot + BTILE - 1) / BTILE;          // 147

    cudaFuncSetAttribute(lstm_behavior_kernel,
                         cudaFuncAttributeMaxDynamicSharedMemorySize, SM_TOT);

    lstm_behavior_kernel<<<grid, NTH, SM_TOT>>>(
        x, w_ih0, w_hh0, b_ih0, b_hh0, w_ih1, w_hh1, b_ih1, b_hh1,
        eng_w1, eng_b1, eng_w2, eng_b2, prop_w1, prop_b1, prop_w2, prop_b2,
        seg_w, seg_b, out, Btot);
}

// round 14
// speedup vs baseline: 3.5183x; 1.0213x over previous
#include <cuda_runtime.h>
#include <cuda_fp16.h>
#include <cstdint>
#include <cstddef>

#define BTILE  14
#define NB     16           // padded batch dim (2 n8 tiles)
#define S_LEN  256
#define F_IN   5
#define HID    64
#define NTH    256

#define KP0    88           // B0 row len (fp16): 80 used
#define KP1    152          // B1 row len (fp16): 128 used
#define GP     260          // gate-bounce row stride (f32 words)
#define KT0    5
#define KT1    8

// SMEM byte offsets (per CTA total 93,440 B -> 2 CTAs/SM)
#define SM_AF1 0                               // aL1 fragment region: 8w*8kt*2mt*512 = 65536
#define SM_B0  65536                           // 16*88*2  = 2816
#define SM_B1  (SM_B0 + NB * KP0 * 2)          // 68352; 16*152*2 = 4864
#define SM_SG  (SM_B1 + NB * KP1 * 2)          // 73216; 16*260*4 = 16640
#define SM_HBF (SM_SG + NB * GP * 4)           // 89856; 14*64*4 = 3584
#define SM_TOT (SM_HBF + BTILE * HID * 4)      // 93440

__device__ __forceinline__ uint32_t smem_u32(const void* p) {
    uint32_t a;
    asm("{ .reg .u64 t; cvta.to.shared.u64 t, %1; cvt.u32.u64 %0, t; }" : "=r"(a) : "l"(p));
    return a;
}
__device__ __forceinline__ uint32_t lds32(uint32_t a) {
    uint32_t v;
    asm volatile("ld.shared.b32 %0, [%1];" : "=r"(v) : "r"(a));
    return v;
}
__device__ __forceinline__ void lds128(uint32_t a, uint32_t* r) {
    asm volatile("ld.shared.v4.b32 {%0,%1,%2,%3}, [%4];"
                 : "=r"(r[0]), "=r"(r[1]), "=r"(r[2]), "=r"(r[3]) : "r"(a));
}

// m16n8k16 row.col f32 += f16*f16 (plain sm_80+ PTX)
__device__ __forceinline__ void mma16816(float* c, const uint32_t* a, const uint32_t* b) {
    asm volatile(
        "mma.sync.aligned.m16n8k16.row.col.f32.f16.f16.f32 "
        "{%0,%1,%2,%3}, {%4,%5,%6,%7}, {%8,%9}, {%0,%1,%2,%3};"
        : "+f"(c[0]), "+f"(c[1]), "+f"(c[2]), "+f"(c[3])
        : "r"(a[0]), "r"(a[1]), "r"(a[2]), "r"(a[3]), "r"(b[0]), "r"(b[1]));
}

// ---------- activations ----------
__device__ __forceinline__ float tanhap(float x) {
    float y;
    asm("tanh.approx.f32 %0, %1;" : "=f"(y) : "f"(x));
    return y;
}
__device__ __forceinline__ float sigm(float x) {
    return fmaf(tanhap(0.5f * x), 0.5f, 0.5f);
}

__device__ __forceinline__ uint32_t packh2(float a, float b) {
    __half2 h = __floats2half2_rn(a, b);
    return *(uint32_t*)&h;
}

__device__ __forceinline__ float mlp_head(const float* __restrict__ hb,
                                          const float* __restrict__ w1,
                                          const float* __restrict__ b1,
                                          const float* __restrict__ w2,
                                          const float* __restrict__ b2) {
    float acc = b2[0];
    #pragma unroll 4
    for (int u = 0; u < 16; u++) {
        float s = b1[u];
        #pragma unroll 8
        for (int k = 0; k < HID; k++) s += hb[k] * w1[u * HID + k];
        acc += fmaxf(s, 0.0f) * w2[u];
    }
    return sigm(acc);
}

__global__ void __launch_bounds__(NTH, 2)
lstm_behavior_kernel(const float* __restrict__ x,
                     const float* __restrict__ w_ih0, const float* __restrict__ w_hh0,
                     const float* __restrict__ b_ih0, const float* __restrict__ b_hh0,
                     const float* __restrict__ w_ih1, const float* __restrict__ w_hh1,
                     const float* __restrict__ b_ih1, const float* __restrict__ b_hh1,
                     const float* __restrict__ eng_w1, const float* __restrict__ eng_b1,
                     const float* __restrict__ eng_w2, const float* __restrict__ eng_b2,
                     const float* __restrict__ prop_w1, const float* __restrict__ prop_b1,
                     const float* __restrict__ prop_w2, const float* __restrict__ prop_b2,
                     const float* __restrict__ seg_w, const float* __restrict__ seg_b,
                     float* __restrict__ out, int Btot) {
    extern __shared__ char smem[];
    const uint32_t sb = smem_u32(smem);
    const int tid  = threadIdx.x;
    const int w    = tid >> 5, lane = tid & 31;
    const int gid  = lane >> 2, tg = lane & 3;

    // ---- zero B tiles (padding rows/cols must be 0) ----
    for (int i = tid; i < (SM_SG - SM_B0) / 4; i += NTH)
        ((uint32_t*)(smem + SM_B0))[i] = 0;

    // ---- fill AF1: layer1 A-fragments in fragment-contiguous order ----
    // entry (w,kt,mt,lane,q): 16B per lane, q*4 within
    for (int fid = tid; fid < 8 * KT1 * 2 * 32 * 4; fid += NTH) {
        int q   = fid & 3;
        int ln  = (fid >> 2) & 31;
        int mtt = (fid >> 7) & 1;
        int ktt = (fid >> 8) & 7;
        int ww  = fid >> 11;
        int gg = ln >> 2, tt = ln & 3;
        int row = ww * 32 + mtt * 16 + gg + (q & 1) * 8;
        int kk  = ktt * 16 + 2 * tt + (q >> 1) * 8;
        float v0 = (kk < 64)     ? w_ih1[row * HID + kk]      : w_hh1[row * HID + kk - 64];
        float v1 = (kk + 1 < 64) ? w_ih1[row * HID + kk + 1]  : w_hh1[row * HID + kk + 1 - 64];
        *(uint32_t*)(smem + SM_AF1 + (fid >> 2) * 16 + q * 4) = packh2(v0, v1);
    }

    // ---- hoist layer0 A-fragments straight from gmem (constant all steps) ----
    uint32_t aL0[KT0][2][4];
    #pragma unroll
    for (int kt = 0; kt < KT0; kt++)
        #pragma unroll
        for (int mt = 0; mt < 2; mt++)
            #pragma unroll
            for (int q = 0; q < 4; q++) {
                int row = w * 32 + mt * 16 + gid + (q & 1) * 8;
                int kk  = kt * 16 + 2 * tg + (q >> 1) * 8;
                float v0 = (kk < 64) ? w_hh0[row * HID + kk]
                         : (kk < 64 + F_IN) ? w_ih0[row * F_IN + kk - 64] : 0.0f;
                int k1 = kk + 1;
                float v1 = (k1 < 64) ? w_hh0[row * HID + k1]
                         : (k1 < 64 + F_IN) ? w_ih0[row * F_IN + k1 - 64] : 0.0f;
                aL0[kt][mt][q] = packh2(v0, v1);
            }

    // ---- update-role constants ----
    const int c  = tid & 63;          // my cell
    const int bq = tid >> 6;          // my 4-batch quarter (16 padded batches)
    float bz0[4], bz1[4];
    #pragma unroll
    for (int m = 0; m < 4; m++) {
        bz0[m] = b_ih0[m * HID + c] + b_hh0[m * HID + c];
        bz1[m] = b_ih1[m * HID + c] + b_hh1[m * HID + c];
    }
    float cA[4], cB[4];
    #pragma unroll
    for (int j = 0; j < 4; j++) { cA[j] = 0.0f; cB[j] = 0.0f; }

    __syncthreads();   // B tiles zeroed (x staging below writes B0)

    // ---- x staging ----
    const float* xptr = nullptr;
    float xreg = 0.0f;
    int xoff = 0;
    if (tid < BTILE * F_IN) {          // tid < 70
        int xb = tid / F_IN, xf = tid - xb * F_IN;
        int gxb = blockIdx.x * BTILE + xb;
        if (gxb > Btot - 1) gxb = Btot - 1;
        xptr = x + (size_t)gxb * (S_LEN * F_IN) + xf;
        xoff = SM_B0 + (xb * KP0 + 64 + xf) * 2;
        *(__half*)(smem + xoff) = __float2half_rn(xptr[0]);
        xreg = xptr[F_IN];
    }
    float* SGf = (float*)(smem + SM_SG);
    float* HBF = (float*)(smem + SM_HBF);
    const uint32_t af1w = sb + SM_AF1 + (uint32_t)w * 8192 + lane * 16;
    __syncthreads();

    float C[2][2][4];
    const int grow = w * 32 + gid;

    for (int t = 0; t < S_LEN; ++t) {
        // ===== phase 1: L0 gemm =====
        #pragma unroll
        for (int a = 0; a < 2; a++)
            #pragma unroll
            for (int b = 0; b < 2; b++)
                #pragma unroll
                for (int e = 0; e < 4; e++) C[a][b][e] = 0.0f;
        #pragma unroll
        for (int kt = 0; kt < KT0; kt++) {
            uint32_t B[2][2];
            #pragma unroll
            for (int nt = 0; nt < 2; nt++) {
                uint32_t ba = sb + SM_B0 + (uint32_t)((nt * 8 + gid) * KP0 + kt * 16 + 2 * tg) * 2;
                B[nt][0] = lds32(ba);
                B[nt][1] = lds32(ba + 16);
            }
            #pragma unroll
            for (int mt = 0; mt < 2; mt++)
                #pragma unroll
                for (int nt = 0; nt < 2; nt++)
                    mma16816(C[mt][nt], aL0[kt][mt], B[nt]);
        }
        #pragma unroll
        for (int mt = 0; mt < 2; mt++) {
            int g = grow + mt * 16;
            #pragma unroll
            for (int nt = 0; nt < 2; nt++) {
                int b = nt * 8 + 2 * tg;
                SGf[b * GP + g]           = C[mt][nt][0];
                SGf[(b + 1) * GP + g]     = C[mt][nt][1];
                SGf[b * GP + g + 8]       = C[mt][nt][2];
                SGf[(b + 1) * GP + g + 8] = C[mt][nt][3];
            }
        }
        __syncthreads();

        // ===== phase 2: L0 update; hA(t) -> B0, B1; stage x(t+1) =====
        #pragma unroll
        for (int j = 0; j < 4; j++) {
            int b = bq * 4 + j;
            const float* gr = SGf + b * GP;
            float gi = gr[c]           + bz0[0];
            float gf = gr[HID + c]     + bz0[1];
            float gg = gr[2 * HID + c] + bz0[2];
            float go = gr[3 * HID + c] + bz0[3];
            float cn = sigm(gf) * cA[j] + sigm(gi) * tanhap(gg);
            cA[j] = cn;
            __half hh = __float2half_rn(sigm(go) * tanhap(cn));
            *(__half*)(smem + SM_B0 + (b * KP0 + c) * 2) = hh;
            *(__half*)(smem + SM_B1 + (b * KP1 + c) * 2) = hh;
        }
        if (tid < BTILE * F_IN) {
            *(__half*)(smem + xoff) = __float2half_rn(xreg);
            int tn = (t + 2 < S_LEN) ? (t + 2) : (S_LEN - 1);
            xreg = xptr[tn * F_IN];
        }
        __syncthreads();

        // ===== phase 3: L1 gemm (A frags via LDS.128 from AF1) =====
        #pragma unroll
        for (int a = 0; a < 2; a++)
            #pragma unroll
            for (int b = 0; b < 2; b++)
                #pragma unroll
                for (int e = 0; e < 4; e++) C[a][b][e] = 0.0f;
        #pragma unroll
        for (int kt = 0; kt < KT1; kt++) {
            uint32_t B[2][2];
            #pragma unroll
            for (int nt = 0; nt < 2; nt++) {
                uint32_t ba = sb + SM_B1 + (uint32_t)((nt * 8 + gid) * KP1 + kt * 16 + 2 * tg) * 2;
                B[nt][0] = lds32(ba);
                B[nt][1] = lds32(ba + 16);
            }
            #pragma unroll
            for (int mt = 0; mt < 2; mt++) {
                uint32_t A[4];
                lds128(af1w + (uint32_t)(kt * 2 + mt) * 512, A);
                #pragma unroll
                for (int nt = 0; nt < 2; nt++)
                    mma16816(C[mt][nt], A, B[nt]);
            }
        }
        #pragma unroll
        for (int mt = 0; mt < 2; mt++) {
            int g = grow + mt * 16;
            #pragma unroll
            for (int nt = 0; nt < 2; nt++) {
                int b = nt * 8 + 2 * tg;
                SGf[b * GP + g]           = C[mt][nt][0];
                SGf[(b + 1) * GP + g]     = C[mt][nt][1];
                SGf[b * GP + g + 8]       = C[mt][nt][2];
                SGf[(b + 1) * GP + g + 8] = C[mt][nt][3];
            }
        }
        __syncthreads();

        // ===== phase 4: L1 update; hB(t) -> B1 cols 64..127 =====
        #pragma unroll
        for (int j = 0; j < 4; j++) {
            int b = bq * 4 + j;
            const float* gr = SGf + b * GP;
            float gi = gr[c]           + bz1[0];
            float gf = gr[HID + c]     + bz1[1];
            float gg = gr[2 * HID + c] + bz1[2];
            float go = gr[3 * HID + c] + bz1[3];
            float cn = sigm(gf) * cB[j] + sigm(gi) * tanhap(gg);
            cB[j] = cn;
            float h = sigm(go) * tanhap(cn);
            *(__half*)(smem + SM_B1 + (b * KP1 + 64 + c) * 2) = __float2half_rn(h);
            if (t == S_LEN - 1 && b < BTILE) HBF[b * HID + c] = h;
        }
        __syncthreads();
    }

    // ---- heads ----
    if (tid < BTILE) {
        int b = blockIdx.x * BTILE + tid;
        if (b < Btot) {
            const float* hb = HBF + tid * HID;
            out[b]        = mlp_head(hb, eng_w1, eng_b1, eng_w2, eng_b2);
            out[Btot + b] = mlp_head(hb, prop_w1, prop_b1, prop_w2, prop_b2);
            #pragma unroll
            for (int j = 0; j < 5; j++) {
                float s = seg_b[j];
                #pragma unroll 8
                for (int k = 0; k < HID; k++) s += hb[k] * seg_w[j * HID + k];
                out[2 * Btot + b * 5 + j] = s;
            }
        }
    }
}

extern "C" void kernel_launch(void* const* d_in, const int* in_sizes, int n_in,
                              void* d_out, int out_size) {
    const float* x       = (const float*)d_in[0];
    const float* w_ih0   = (const float*)d_in[1];
    const float* w_hh0   = (const float*)d_in[2];
    const float* b_ih0   = (const float*)d_in[3];
    const float* b_hh0   = (const float*)d_in[4];
    const float* w_ih1   = (const float*)d_in[5];
    const float* w_hh1   = (const float*)d_in[6];
    const float* b_ih1   = (const float*)d_in[7];
    const float* b_hh1   = (const float*)d_in[8];
    const float* eng_w1  = (const float*)d_in[9];
    const float* eng_b1  = (const float*)d_in[10];
    const float* eng_w2  = (const float*)d_in[11];
    const float* eng_b2  = (const float*)d_in[12];
    const float* prop_w1 = (const float*)d_in[13];
    const float* prop_b1 = (const float*)d_in[14];
    const float* prop_w2 = (const float*)d_in[15];
    const float* prop_b2 = (const float*)d_in[16];
    const float* seg_w   = (const float*)d_in[17];
    const float* seg_b   = (const float*)d_in[18];
    float* out = (float*)d_out;

    int Btot = in_sizes[0] / (S_LEN * F_IN);        // 4096
    int grid = (Btot + BTILE - 1) / BTILE;          // 293

    cudaFuncSetAttribute(lstm_behavior_kernel,
                         cudaFuncAttributeMaxDynamicSharedMemorySize, SM_TOT);

    lstm_behavior_kernel<<<grid, NTH, SM_TOT>>>(
        x, w_ih0, w_hh0, b_ih0, b_hh0, w_ih1, w_hh1, b_ih1, b_hh1,
        eng_w1, eng_b1, eng_w2, eng_b2, prop_w1, prop_b1, prop_w2, prop_b2,
        seg_w, seg_b, out, Btot);
}

// round 15
// speedup vs baseline: 4.7102x; 1.3388x over previous
#include <cuda_runtime.h>
#include <cuda_fp16.h>
#include <cstdint>
#include <cstddef>

#define BTILE  14
#define NB     16           // padded batch dim (2 n8 tiles)
#define S_LEN  256
#define F_IN   5
#define HID    64
#define NTH    256

#define KP0    88           // B0 row len (fp16): 80 used
#define KP1    152          // B1 row len (fp16): 128 used
#define KT0    5
#define KT1    8

// SMEM byte offsets (per CTA 79,616 B -> 2 CTAs/SM)
#define SM_AF1 0                               // layer1 A-fragments: 8w*8kt*2mt*512 = 65536
#define SM_B0A 65536                           // B0 ping: 16*88*2 = 2816
#define SM_B0B (SM_B0A + NB * KP0 * 2)         // B0 pong
#define SM_B1  (SM_B0B + NB * KP0 * 2)         // 16*152*2 = 4864
#define SM_HBF (SM_B1 + NB * KP1 * 2)          // 14*64*4 = 3584
#define SM_TOT (SM_HBF + BTILE * HID * 4)      // 79616

__device__ __forceinline__ uint32_t smem_u32(const void* p) {
    uint32_t a;
    asm("{ .reg .u64 t; cvta.to.shared.u64 t, %1; cvt.u32.u64 %0, t; }" : "=r"(a) : "l"(p));
    return a;
}
__device__ __forceinline__ uint32_t lds32(uint32_t a) {
    uint32_t v;
    asm volatile("ld.shared.b32 %0, [%1];" : "=r"(v) : "r"(a));
    return v;
}
__device__ __forceinline__ void lds128(uint32_t a, uint32_t* r) {
    asm volatile("ld.shared.v4.b32 {%0,%1,%2,%3}, [%4];"
                 : "=r"(r[0]), "=r"(r[1]), "=r"(r[2]), "=r"(r[3]) : "r"(a));
}

// m16n8k16 row.col f32 += f16*f16 (plain sm_80+ PTX)
__device__ __forceinline__ void mma16816(float* c, const uint32_t* a, const uint32_t* b) {
    asm volatile(
        "mma.sync.aligned.m16n8k16.row.col.f32.f16.f16.f32 "
        "{%0,%1,%2,%3}, {%4,%5,%6,%7}, {%8,%9}, {%0,%1,%2,%3};"
        : "+f"(c[0]), "+f"(c[1]), "+f"(c[2]), "+f"(c[3])
        : "r"(a[0]), "r"(a[1]), "r"(a[2]), "r"(a[3]), "r"(b[0]), "r"(b[1]));
}

// ---------- activations ----------
__device__ __forceinline__ float tanhap(float x) {
    float y;
    asm("tanh.approx.f32 %0, %1;" : "=f"(y) : "f"(x));
    return y;
}
__device__ __forceinline__ float sigm(float x) {
    return fmaf(tanhap(0.5f * x), 0.5f, 0.5f);
}
__device__ __forceinline__ uint32_t packh2(float a, float b) {
    __half2 h = __floats2half2_rn(a, b);
    return *(uint32_t*)&h;
}

__device__ __forceinline__ float mlp_head(const float* __restrict__ hb,
                                          const float* __restrict__ w1,
                                          const float* __restrict__ b1,
                                          const float* __restrict__ w2,
                                          const float* __restrict__ b2) {
    float acc = b2[0];
    #pragma unroll 4
    for (int u = 0; u < 16; u++) {
        float s = b1[u];
        #pragma unroll 8
        for (int k = 0; k < HID; k++) s += hb[k] * w1[u * HID + k];
        acc += fmaxf(s, 0.0f) * w2[u];
    }
    return sigm(acc);
}

__global__ void __launch_bounds__(NTH, 2)
lstm_behavior_kernel(const float* __restrict__ x,
                     const float* __restrict__ w_ih0, const float* __restrict__ w_hh0,
                     const float* __restrict__ b_ih0, const float* __restrict__ b_hh0,
                     const float* __restrict__ w_ih1, const float* __restrict__ w_hh1,
                     const float* __restrict__ b_ih1, const float* __restrict__ b_hh1,
                     const float* __restrict__ eng_w1, const float* __restrict__ eng_b1,
                     const float* __restrict__ eng_w2, const float* __restrict__ eng_b2,
                     const float* __restrict__ prop_w1, const float* __restrict__ prop_b1,
                     const float* __restrict__ prop_w2, const float* __restrict__ prop_b2,
                     const float* __restrict__ seg_w, const float* __restrict__ seg_b,
                     float* __restrict__ out, int Btot) {
    extern __shared__ char smem[];
    const uint32_t sb = smem_u32(smem);
    const int tid  = threadIdx.x;
    const int w    = tid >> 5, lane = tid & 31;
    const int gid  = lane >> 2, tg = lane & 3;
    const int c    = w * 8 + gid;       // my cell (output permutation)

    // ---- zero B tiles ----
    for (int i = tid; i < (SM_HBF - SM_B0A) / 4; i += NTH)
        ((uint32_t*)(smem + SM_B0A))[i] = 0;

    // ---- fill AF1: layer1 A-fragments, PERMUTED rows ----
    // MMA row (ww*32 + mtt*16 + (q&1)*8 + g8) <- gate m=2*mtt+(q&1) of cell ww*8+g8
    // i.e. PyTorch row  m*64 + ww*8 + g8
    for (int fid = tid; fid < 8 * KT1 * 2 * 32 * 4; fid += NTH) {
        int q   = fid & 3;
        int ln  = (fid >> 2) & 31;
        int mtt = (fid >> 7) & 1;
        int ktt = (fid >> 8) & 7;
        int ww  = fid >> 11;
        int g8 = ln >> 2, tt = ln & 3;
        int row = (2 * mtt + (q & 1)) * 64 + ww * 8 + g8;      // PyTorch gate row
        int kk  = ktt * 16 + 2 * tt + (q >> 1) * 8;
        float v0 = (kk < 64)     ? w_ih1[row * HID + kk]     : w_hh1[row * HID + kk - 64];
        float v1 = (kk + 1 < 64) ? w_ih1[row * HID + kk + 1] : w_hh1[row * HID + kk + 1 - 64];
        *(uint32_t*)(smem + SM_AF1 + (fid >> 2) * 16 + q * 4) = packh2(v0, v1);
    }

    // ---- hoist layer0 A-fragments (permuted rows) straight from gmem ----
    uint32_t aL0[KT0][2][4];
    #pragma unroll
    for (int kt = 0; kt < KT0; kt++)
        #pragma unroll
        for (int mt = 0; mt < 2; mt++)
            #pragma unroll
            for (int q = 0; q < 4; q++) {
                int row = (2 * mt + (q & 1)) * 64 + c;          // PyTorch gate row
                int kk  = kt * 16 + 2 * tg + (q >> 1) * 8;
                float v0 = (kk < 64) ? w_hh0[row * HID + kk]
                         : (kk < 64 + F_IN) ? w_ih0[row * F_IN + kk - 64] : 0.0f;
                int k1 = kk + 1;
                float v1 = (k1 < 64) ? w_hh0[row * HID + k1]
                         : (k1 < 64 + F_IN) ? w_ih0[row * F_IN + k1 - 64] : 0.0f;
                aL0[kt][mt][q] = packh2(v0, v1);
            }

    // ---- per-cell biases (i,f,g,o) ----
    float bz0[4], bz1[4];
    #pragma unroll
    for (int m = 0; m < 4; m++) {
        bz0[m] = b_ih0[m * HID + c] + b_hh0[m * HID + c];
        bz1[m] = b_ih1[m * HID + c] + b_hh1[m * HID + c];
    }
    float cA[4], cB[4];     // c-state for my 4 batches: idx nt*2+p, b = nt*8+2tg+p
    #pragma unroll
    for (int j = 0; j < 4; j++) { cA[j] = 0.0f; cB[j] = 0.0f; }

    __syncthreads();   // B tiles zeroed before x staging writes B0A

    // ---- x staging ----
    const float* xptr = nullptr;
    float xreg = 0.0f;
    int xrel = 0;
    if (tid < BTILE * F_IN) {          // tid < 70
        int xb = tid / F_IN, xf = tid - xb * F_IN;
        int gxb = blockIdx.x * BTILE + xb;
        if (gxb > Btot - 1) gxb = Btot - 1;
        xptr = x + (size_t)gxb * (S_LEN * F_IN) + xf;
        xrel = (xb * KP0 + 64 + xf) * 2;
        *(__half*)(smem + SM_B0A + xrel) = __float2half_rn(xptr[0]);   // x(0) -> ping
        xreg = xptr[F_IN];
    }
    float* HBF = (float*)(smem + SM_HBF);
    const uint32_t af1w = sb + SM_AF1 + (uint32_t)w * 8192 + lane * 16;
    __syncthreads();

    float C[2][2][4];
    const int b2tg = 2 * tg;

    for (int t = 0; t < S_LEN; ++t) {
        const int b0rd = (t & 1) ? SM_B0B : SM_B0A;     // hA(t-1), x(t)
        const int b0wr = (t & 1) ? SM_B0A : SM_B0B;     // hA(t), x(t+1)

        // ===== P1: L0 gemm (reads B0[t&1] only) =====
        #pragma unroll
        for (int a = 0; a < 2; a++)
            #pragma unroll
            for (int b = 0; b < 2; b++)
                #pragma unroll
                for (int e = 0; e < 4; e++) C[a][b][e] = 0.0f;
        #pragma unroll
        for (int kt = 0; kt < KT0; kt++) {
            uint32_t B[2][2];
            #pragma unroll
            for (int nt = 0; nt < 2; nt++) {
                uint32_t ba = sb + b0rd + (uint32_t)((nt * 8 + gid) * KP0 + kt * 16 + b2tg) * 2;
                B[nt][0] = lds32(ba);
                B[nt][1] = lds32(ba + 16);
            }
            #pragma unroll
            for (int mt = 0; mt < 2; mt++)
                #pragma unroll
                for (int nt = 0; nt < 2; nt++)
                    mma16816(C[mt][nt], aL0[kt][mt], B[nt]);
        }

        // ===== P2: L0 update IN REGISTERS; hA(t)->B0[wr]+B1; x(t+1)->B0[wr] =====
        // C[0][nt][p]=i, C[0][nt][2+p]=f, C[1][nt][p]=g, C[1][nt][2+p]=o  (batch nt*8+2tg+p)
        #pragma unroll
        for (int nt = 0; nt < 2; nt++)
            #pragma unroll
            for (int p = 0; p < 2; p++) {
                int j = nt * 2 + p;
                int b = nt * 8 + b2tg + p;
                float gi = C[0][nt][p]     + bz0[0];
                float gf = C[0][nt][2 + p] + bz0[1];
                float gg = C[1][nt][p]     + bz0[2];
                float go = C[1][nt][2 + p] + bz0[3];
                float cn = sigm(gf) * cA[j] + sigm(gi) * tanhap(gg);
                cA[j] = cn;
                __half hh = __float2half_rn(sigm(go) * tanhap(cn));
                *(__half*)(smem + b0wr + (b * KP0 + c) * 2) = hh;
                *(__half*)(smem + SM_B1 + (b * KP1 + c) * 2) = hh;
            }
        if (tid < BTILE * F_IN) {
            *(__half*)(smem + b0wr + xrel) = __float2half_rn(xreg);
            int tn = (t + 2 < S_LEN) ? (t + 2) : (S_LEN - 1);
            xreg = xptr[tn * F_IN];
        }
        __syncthreads();                 // hA(t) visible in B1 / B0[wr]

        // ===== P3: L1 gemm (reads B1: hA(t) cols 0-63, hB(t-1) cols 64-127) =====
        #pragma unroll
        for (int a = 0; a < 2; a++)
            #pragma unroll
            for (int b = 0; b < 2; b++)
                #pragma unroll
                for (int e = 0; e < 4; e++) C[a][b][e] = 0.0f;
        #pragma unroll
        for (int kt = 0; kt < KT1; kt++) {
            uint32_t B[2][2];
            #pragma unroll
            for (int nt = 0; nt < 2; nt++) {
                uint32_t ba = sb + SM_B1 + (uint32_t)((nt * 8 + gid) * KP1 + kt * 16 + b2tg) * 2;
                B[nt][0] = lds32(ba);
                B[nt][1] = lds32(ba + 16);
            }
            #pragma unroll
            for (int mt = 0; mt < 2; mt++) {
                uint32_t A[4];
                lds128(af1w + (uint32_t)(kt * 2 + mt) * 512, A);
                #pragma unroll
                for (int nt = 0; nt < 2; nt++)
                    mma16816(C[mt][nt], A, B[nt]);
            }
        }
        __syncthreads();                 // all done reading B1 (hB(t-1))

        // ===== P4: L1 update IN REGISTERS; hB(t) -> B1 cols 64-127 =====
        #pragma unroll
        for (int nt = 0; nt < 2; nt++)
            #pragma unroll
            for (int p = 0; p < 2; p++) {
                int j = nt * 2 + p;
                int b = nt * 8 + b2tg + p;
                float gi = C[0][nt][p]     + bz1[0];
                float gf = C[0][nt][2 + p] + bz1[1];
                float gg = C[1][nt][p]     + bz1[2];
                float go = C[1][nt][2 + p] + bz1[3];
                float cn = sigm(gf) * cB[j] + sigm(gi) * tanhap(gg);
                cB[j] = cn;
                float h = sigm(go) * tanhap(cn);
                *(__half*)(smem + SM_B1 + (b * KP1 + 64 + c) * 2) = __float2half_rn(h);
                if (t == S_LEN - 1 && b < BTILE) HBF[b * HID + c] = h;
            }
        // hB(t) visibility for P3(t+1) covered by P2(t+1)'s __syncthreads()
    }
    __syncthreads();

    // ---- heads ----
    if (tid < BTILE) {
        int b = blockIdx.x * BTILE + tid;
        if (b < Btot) {
            const float* hb = HBF + tid * HID;
            out[b]        = mlp_head(hb, eng_w1, eng_b1, eng_w2, eng_b2);
            out[Btot + b] = mlp_head(hb, prop_w1, prop_b1, prop_w2, prop_b2);
            #pragma unroll
            for (int j = 0; j < 5; j++) {
                float s = seg_b[j];
                #pragma unroll 8
                for (int k = 0; k < HID; k++) s += hb[k] * seg_w[j * HID + k];
                out[2 * Btot + b * 5 + j] = s;
            }
        }
    }
}

extern "C" void kernel_launch(void* const* d_in, const int* in_sizes, int n_in,
                              void* d_out, int out_size) {
    const float* x       = (const float*)d_in[0];
    const float* w_ih0   = (const float*)d_in[1];
    const float* w_hh0   = (const float*)d_in[2];
    const float* b_ih0   = (const float*)d_in[3];
    const float* b_hh0   = (const float*)d_in[4];
    const float* w_ih1   = (const float*)d_in[5];
    const float* w_hh1   = (const float*)d_in[6];
    const float* b_ih1   = (const float*)d_in[7];
    const float* b_hh1   = (const float*)d_in[8];
    const float* eng_w1  = (const float*)d_in[9];
    const float* eng_b1  = (const float*)d_in[10];
    const float* eng_w2  = (const float*)d_in[11];
    const float* eng_b2  = (const float*)d_in[12];
    const float* prop_w1 = (const float*)d_in[13];
    const float* prop_b1 = (const float*)d_in[14];
    const float* prop_w2 = (const float*)d_in[15];
    const float* prop_b2 = (const float*)d_in[16];
    const float* seg_w   = (const float*)d_in[17];
    const float* seg_b   = (const float*)d_in[18];
    float* out = (float*)d_out;

    int Btot = in_sizes[0] / (S_LEN * F_IN);        // 4096
    int grid = (Btot + BTILE - 1) / BTILE;          // 293

    cudaFuncSetAttribute(lstm_behavior_kernel,
                         cudaFuncAttributeMaxDynamicSharedMemorySize, SM_TOT);

    lstm_behavior_kernel<<<grid, NTH, SM_TOT>>>(
        x, w_ih0, w_hh0, b_ih0, b_hh0, w_ih1, w_hh1, b_ih1, b_hh1,
        eng_w1, eng_b1, eng_w2, eng_b2, prop_w1, prop_b1, prop_w2, prop_b2,
        seg_w, seg_b, out, Btot);
}